// round 7
// baseline (speedup 1.0000x reference)
#include <cuda_runtime.h>
#include <cuda_fp16.h>

#define NN      50000      // nodes
#define NIN     128        // node in-dim
#define NOUT    64         // node out-dim
#define EIN     32         // edge feat dim
#define NE      400000     // undirected edges
#define ND      (2*NE)     // directed edges
#define ALPHA_L 0.2f
#define EPSV    1e-12f
#define NPART   256
#define FULLM   0xffffffffu
#define NSP     132        // padded node row stride in k1 smem (floats)

// ---------------- scratch (device globals) -------------------------------------
__device__ __align__(16) __half g_hvh[NN * NOUT]; // h_v in fp16 (gather path)
__device__ __align__(16) float g_msg[NN * NOUT];  // segment sum by src (fp32)
__device__ float  g_s1[NN];
__device__ float  g_s2[NN];
__device__ float  g_hn[NN];
__device__ float  g_attsum[NN];
__device__ float  g_lr[ND];
__device__ double g_psum[NPART];
__device__ double g_psq[NPART];

// vector RED: 4 floats in one L2 atomic op (sm_90+)
__device__ __forceinline__ void red_v4(float* addr, float4 v) {
    asm volatile("red.global.add.v4.f32 [%0], {%1,%2,%3,%4};"
                 :: "l"(addr), "f"(v.x), "f"(v.y), "f"(v.z), "f"(v.w) : "memory");
}
// packed fp32x2 FMA (PTX-only path to FFMA2)
__device__ __forceinline__ void fma2(unsigned long long& d,
                                     unsigned long long a,
                                     unsigned long long b) {
    asm("fma.rn.f32x2 %0, %1, %2, %0;" : "+l"(d) : "l"(a), "l"(b));
}
__device__ __forceinline__ unsigned long long pack2(float v) {
    unsigned long long r; unsigned int u = __float_as_uint(v);
    asm("mov.b64 %0, {%1, %1};" : "=l"(r) : "r"(u));
    return r;
}
__device__ __forceinline__ float2 unpack2(unsigned long long p) {
    unsigned int lo, hi;
    asm("mov.b64 {%0, %1}, %2;" : "=r"(lo), "=r"(hi) : "l"(p));
    return make_float2(__uint_as_float(lo), __uint_as_float(hi));
}
__device__ __forceinline__ __half2 u32_as_h2(unsigned int u) {
    __half2 h; *reinterpret_cast<unsigned int*>(&h) = u; return h;
}

// ---------------- k1: zero prologue + FFMA2 GEMM + scalars + out[:,0:64] + hvh ---
// 256 threads, 128 nodes/block. Thread tile: 4 nodes x 8 cols (4 packed pairs).
__global__ void k1_gemm(const float* __restrict__ nf,
                        const float* __restrict__ W,
                        const float* __restrict__ b,
                        const float* __restrict__ an,
                        float* __restrict__ out) {
    extern __shared__ float sm[];
    float* Ws = sm;              // 128*64  = 8192 floats (32 KB)
    float* Ns = sm + 8192;       // 128*132 = 16896 floats (66 KB)
    int tid = threadIdx.x;
    int base = blockIdx.x * 128;
    int gid = blockIdx.x * 256 + tid;

    // prologue: zero attsum + variance partials (grid = 100096 >= NN)
    if (gid < NN) g_attsum[gid] = 0.f;
    if (gid < NPART) { g_psum[gid] = 0.0; g_psq[gid] = 0.0; }

    for (int i = tid; i < (NIN * NOUT) / 4; i += 256)
        ((float4*)Ws)[i] = ((const float4*)W)[i];
    for (int i = tid; i < 128 * 32; i += 256) {
        int r = i >> 5, c = i & 31;
        int node = base + r;
        float4 v = make_float4(0.f, 0.f, 0.f, 0.f);
        if (node < NN) v = ((const float4*)nf)[(long)node * 32 + c];
        *(float4*)(Ns + r * NSP + c * 4) = v;
    }
    __syncthreads();

    int cg = tid & 7;            // cols cg*8 .. cg*8+7
    int ng = tid >> 3;           // nodes ng*4 .. ng*4+3
    const float* nb = Ns + ng * 4 * NSP;

    unsigned long long acc[4][4];
#pragma unroll
    for (int n = 0; n < 4; n++)
#pragma unroll
        for (int p = 0; p < 4; p++) acc[n][p] = 0ULL;

#pragma unroll 4
    for (int k = 0; k < NIN; k++) {
        const unsigned long long* wrow =
            (const unsigned long long*)(Ws + k * NOUT + cg * 8);
        unsigned long long w0 = wrow[0], w1 = wrow[1],
                           w2 = wrow[2], w3 = wrow[3];
#pragma unroll
        for (int n = 0; n < 4; n++) {
            unsigned long long av = pack2(nb[n * NSP + k]);
            fma2(acc[n][0], av, w0);
            fma2(acc[n][1], av, w1);
            fma2(acc[n][2], av, w2);
            fma2(acc[n][3], av, w3);
        }
    }

    float4 bv0 = *(const float4*)&b[cg * 8];
    float4 bv1 = *(const float4*)&b[cg * 8 + 4];
    __syncthreads();                         // done reading Ns; reuse as hvt
    float* hvt = Ns;                         // 128 x 64 fp32 tile
#pragma unroll
    for (int n = 0; n < 4; n++) {
        float2 c01 = unpack2(acc[n][0]);
        float2 c23 = unpack2(acc[n][1]);
        float2 c45 = unpack2(acc[n][2]);
        float2 c67 = unpack2(acc[n][3]);
        float4 lo = make_float4(c01.x + bv0.x, c01.y + bv0.y,
                                c23.x + bv0.z, c23.y + bv0.w);
        float4 hi = make_float4(c45.x + bv1.x, c45.y + bv1.y,
                                c67.x + bv1.z, c67.y + bv1.w);
        int nl = ng * 4 + n;
        int node = base + nl;
        if (node < NN) {
            ((float4*)out)[(long)node * 32 + cg * 2]     = lo;  // cols 0..63
            ((float4*)out)[(long)node * 32 + cg * 2 + 1] = hi;
            __half2 h01 = __floats2half2_rn(lo.x, lo.y);
            __half2 h23 = __floats2half2_rn(lo.z, lo.w);
            __half2 h45 = __floats2half2_rn(hi.x, hi.y);
            __half2 h67 = __floats2half2_rn(hi.z, hi.w);
            uint4 hv;
            hv.x = *reinterpret_cast<unsigned int*>(&h01);
            hv.y = *reinterpret_cast<unsigned int*>(&h23);
            hv.z = *reinterpret_cast<unsigned int*>(&h45);
            hv.w = *reinterpret_cast<unsigned int*>(&h67);
            ((uint4*)g_hvh)[(long)node * 8 + cg] = hv;
        }
        *(float4*)&hvt[nl * NOUT + cg * 8]     = lo;
        *(float4*)&hvt[nl * NOUT + cg * 8 + 4] = hi;
    }
    __syncthreads();

    // per-node scalars: 8 warps x 16 nodes each
    int wp = tid >> 5, l = tid & 31;
    float a1x = __ldg(&an[2*l]),      a1y = __ldg(&an[2*l+1]);
    float a2x = __ldg(&an[64 + 2*l]), a2y = __ldg(&an[64 + 2*l+1]);
#pragma unroll
    for (int i = 0; i < 16; i++) {
        int n = wp * 16 + i;
        int node = base + n;
        float2 h = ((const float2*)hvt)[n * 32 + l];
        float s1 = h.x * a1x + h.y * a1y;
        float s2 = h.x * a2x + h.y * a2y;
        float sq = h.x * h.x + h.y * h.y;
#pragma unroll
        for (int o = 16; o; o >>= 1) {
            s1 += __shfl_down_sync(FULLM, s1, o);
            s2 += __shfl_down_sync(FULLM, s2, o);
            sq += __shfl_down_sync(FULLM, sq, o);
        }
        if (l == 0 && node < NN) {
            g_s1[node] = s1; g_s2[node] = s2; g_hn[node] = sqrtf(sq);
        }
    }
}

// ---------------- kE: edge dot + attention (both dirs) + zero g_msg --------------
__global__ void kE_edge(const float* __restrict__ ef,
                        const float* __restrict__ an,
                        const int* __restrict__ p) {
    long gid = (long)blockIdx.x * blockDim.x + threadIdx.x;
    ((float4*)g_msg)[gid] = make_float4(0.f, 0.f, 0.f, 0.f);

    int w = (int)(gid >> 5);
    int l = threadIdx.x & 31;
    int row0 = w * 16;                       // NE % 16 == 0
    const float4* ef4 = (const float4*)ef + (long)row0 * 8;
    float4 v0 = __ldg(&ef4[l]);
    float4 v1 = __ldg(&ef4[32 + l]);
    float4 v2 = __ldg(&ef4[64 + l]);
    float4 v3 = __ldg(&ef4[96 + l]);
    const float* a3 = an + 2 * NOUT;
    int q = l & 7;
    float ax = __ldg(&a3[4*q]),   ay = __ldg(&a3[4*q+1]);
    float az = __ldg(&a3[4*q+2]), aw = __ldg(&a3[4*q+3]);
    float s0 = v0.x*ax + v0.y*ay + v0.z*az + v0.w*aw;
    float s1 = v1.x*ax + v1.y*ay + v1.z*az + v1.w*aw;
    float s2 = v2.x*ax + v2.y*ay + v2.z*az + v2.w*aw;
    float s3 = v3.x*ax + v3.y*ay + v3.z*az + v3.w*aw;
#pragma unroll
    for (int o = 4; o; o >>= 1) {
        s0 += __shfl_xor_sync(FULLM, s0, o);
        s1 += __shfl_xor_sync(FULLM, s1, o);
        s2 += __shfl_xor_sync(FULLM, s2, o);
        s3 += __shfl_xor_sync(FULLM, s3, o);
    }
    int e = l & 15, dir = l >> 4;
    int srcl = (e & 3) << 3;
    float t0 = __shfl_sync(FULLM, s0, srcl);
    float t1 = __shfl_sync(FULLM, s1, srcl);
    float t2 = __shfl_sync(FULLM, s2, srcl);
    float t3 = __shfl_sync(FULLM, s3, srcl);
    int c = e >> 2;
    float tu = (c == 0) ? t0 : (c == 1) ? t1 : (c == 2) ? t2 : t3;

    int u = row0 + e;
    int2 xy = __ldg(&((const int2*)p)[u]);
    int src = dir ? xy.y : xy.x;
    int dst = dir ? xy.x : xy.y;
    float lg = __ldg(&g_s1[src]) + __ldg(&g_s2[dst]) + tu;
    float lr = (lg > 0.f) ? lg : ALPHA_L * lg;
    g_lr[u + dir * NE] = lr;
    atomicAdd(&g_attsum[src], __expf(lr));
}

// ---------------- k4: msg scatter (fp16 gather, vector RED) + var partials -------
#define ED 8   // undirected edges per warp
__global__ void k4_scatter(const int* __restrict__ p) {
    __shared__ float ssum[8], ssq[8];
    int warp = (blockIdx.x * blockDim.x + threadIdx.x) >> 5;
    int l = threadIdx.x & 31;
    int half = l >> 4, q = l & 15;
    long base = (long)warp * ED;           // NE % ED == 0

    int2  xy[ED];
    float l1[ED], l2[ED];
#pragma unroll
    for (int e = 0; e < ED; e++) {
        long u = base + e;
        xy[e] = __ldg(&((const int2*)p)[u]);
        l1[e] = __ldg(&g_lr[u]);
        l2[e] = __ldg(&g_lr[u + NE]);
    }
    float a1[ED], a2[ED];
    uint2 h[ED];
#pragma unroll
    for (int e = 0; e < ED; e++) {
        a1[e] = __ldg(&g_attsum[xy[e].x]);
        a2[e] = __ldg(&g_attsum[xy[e].y]);
        int gdst = half ? xy[e].x : xy[e].y;
        h[e] = __ldg(&((const uint2*)g_hvh)[(long)gdst * 16 + q]);  // 4 halves
    }
    float vs = 0.f, vq = 0.f;
#pragma unroll
    for (int e = 0; e < ED; e++) {
        float an1 = l1[e] - __logf(a1[e]);
        float an2 = l2[e] - __logf(a2[e]);
        float an  = half ? an2 : an1;
        int gsrc  = half ? xy[e].y : xy[e].x;
        float2 f01 = __half22float2(u32_as_h2(h[e].x));
        float2 f23 = __half22float2(u32_as_h2(h[e].y));
        red_v4(&g_msg[(long)gsrc * NOUT + q * 4],
               make_float4(f01.x * an, f01.y * an, f23.x * an, f23.y * an));
        if (l == 0) { vs += an1 + an2; vq += an1 * an1 + an2 * an2; }
    }
    if (l == 0) { ssum[threadIdx.x >> 5] = vs; ssq[threadIdx.x >> 5] = vq; }
    __syncthreads();
    if (threadIdx.x == 0) {
        float bs = 0.f, bq = 0.f;
#pragma unroll
        for (int i = 0; i < 8; i++) { bs += ssum[i]; bq += ssq[i]; }
        atomicAdd(&g_psum[blockIdx.x & (NPART - 1)], (double)bs);
        atomicAdd(&g_psq [blockIdx.x & (NPART - 1)], (double)bq);
    }
}

// ---------------- k6: agg normalize + out[:,64:128]; block 0 also does variance --
__global__ void k6_final(float* __restrict__ out, const float* __restrict__ scale) {
    __shared__ double sd[NPART], qd[NPART];
    int lane = threadIdx.x & 31;
    int node = ((blockIdx.x * blockDim.x + threadIdx.x) >> 4);  // 16 lanes/node
    int q = lane & 15;
    float4 m = __ldg(&((const float4*)g_msg)[(long)node * 16 + q]);
    float sq = m.x*m.x + m.y*m.y + m.z*m.z + m.w*m.w;
#pragma unroll
    for (int o = 8; o; o >>= 1) sq += __shfl_xor_sync(FULLM, sq, o);
    float r = __ldg(&g_hn[node]) * __ldg(scale) / fmaxf(sqrtf(sq), EPSV);
    ((float4*)(out + (long)node * 128))[16 + q] =
        make_float4(m.x * r, m.y * r, m.z * r, m.w * r);

    if (blockIdx.x == 0) {
        int t = threadIdx.x;
        sd[t] = g_psum[t]; qd[t] = g_psq[t];
        __syncthreads();
        for (int o = NPART / 2; o; o >>= 1) {
            if (t < o) { sd[t] += sd[t + o]; qd[t] += qd[t + o]; }
            __syncthreads();
        }
        if (t == 0) {
            double E = (double)ND;
            double var = (qd[0] - sd[0] * sd[0] / E) / (E - 1.0);
            out[(long)NN * 128] = (float)var;
        }
    }
}

// ---------------- launch --------------------------------------------------------------
extern "C" void kernel_launch(void* const* d_in, const int* in_sizes, int n_in,
                              void* d_out, int out_size) {
    const float* nf    = (const float*)d_in[0];
    const float* ef    = (const float*)d_in[1];
    const int*   edges = (const int*)  d_in[2];
    const float* W     = (const float*)d_in[3];
    const float* b     = (const float*)d_in[4];
    const float* an    = (const float*)d_in[5];
    const float* scale = (const float*)d_in[6];
    float* out = (float*)d_out;

    const int k1_smem = (8192 + 128 * NSP) * 4;  // ~98.8 KB
    cudaFuncSetAttribute(k1_gemm, cudaFuncAttributeMaxDynamicSharedMemorySize, k1_smem);

    k1_gemm   <<<(NN + 127)/128, 256, k1_smem>>>(nf, W, b, an, out);
    kE_edge   <<<NE/16/8, 256>>>(ef, an, edges);     // 3125 blocks
    k4_scatter<<<NE/(8*ED), 256>>>(edges);           // 6250 blocks
    k6_final  <<<NN/16, 256>>>(out, scale);          // 3125 blocks
}

// round 8
// speedup vs baseline: 1.1600x; 1.1600x over previous
#include <cuda_runtime.h>
#include <cuda_fp16.h>

#define NN      50000      // nodes
#define NIN     128        // node in-dim
#define NOUT    64         // node out-dim
#define EIN     32         // edge feat dim
#define NE      400000     // undirected edges
#define ND      (2*NE)     // directed edges
#define ALPHA_L 0.2f
#define EPSV    1e-12f
#define NPART   256
#define FULLM   0xffffffffu

// ---------------- scratch (device globals) -------------------------------------
__device__ __align__(16) __half g_hvh[NN * NOUT]; // h_v in fp16 (gather path)
__device__ __align__(16) float g_msg[NN * NOUT];  // segment sum by src (fp32)
__device__ float  g_s1[NN];
__device__ float  g_s2[NN];
__device__ float  g_hn[NN];
__device__ float  g_attsum[NN];
__device__ float  g_lr[ND];
__device__ double g_psum[NPART];
__device__ double g_psq[NPART];

// vector RED: 4 floats in one L2 atomic op (sm_90+)
__device__ __forceinline__ void red_v4(float* addr, float4 v) {
    asm volatile("red.global.add.v4.f32 [%0], {%1,%2,%3,%4};"
                 :: "l"(addr), "f"(v.x), "f"(v.y), "f"(v.z), "f"(v.w) : "memory");
}
__device__ __forceinline__ __half2 u32_as_h2(unsigned int u) {
    __half2 h; *reinterpret_cast<unsigned int*>(&h) = u; return h;
}

// ---------------- k1: zero prologue + GEMM + scalars + out[:,0:64] + hvh ---------
// 256 threads, 128 nodes/block, thread tile 8 nodes x 4 cols (round-6 FFMA core).
__global__ void k1_gemm(const float* __restrict__ nf,
                        const float* __restrict__ W,
                        const float* __restrict__ b,
                        const float* __restrict__ an,
                        float* __restrict__ out) {
    extern __shared__ float sm[];
    float* Ws = sm;            // 8192 floats (32 KB)
    float* Ns = sm + 8192;     // 16384 floats (64 KB)
    int tid = threadIdx.x;
    int base = blockIdx.x * 128;
    int gid = blockIdx.x * 256 + tid;

    // prologue: zero attsum + variance partials (grid = 100096 >= NN)
    if (gid < NN) g_attsum[gid] = 0.f;
    if (gid < NPART) { g_psum[gid] = 0.0; g_psq[gid] = 0.0; }

    for (int i = tid; i < (NIN * NOUT) / 4; i += 256)
        ((float4*)Ws)[i] = ((const float4*)W)[i];
    for (int i = tid; i < (128 * NIN) / 4; i += 256) {
        int node = base + (i >> 5);
        float4 v = make_float4(0.f, 0.f, 0.f, 0.f);
        if (node < NN) v = ((const float4*)nf)[(long)node * 32 + (i & 31)];
        ((float4*)Ns)[i] = v;
    }
    __syncthreads();

    int cg = tid & 15;         // 4 cols each
    int ng = tid >> 4;         // 8 nodes each
    const float* nb = &Ns[ng * 8 * NIN];

    float4 acc[8];
#pragma unroll
    for (int n = 0; n < 8; n++) acc[n] = make_float4(0.f, 0.f, 0.f, 0.f);

#pragma unroll 4
    for (int k = 0; k < NIN; k++) {
        float4 wv = *(const float4*)&Ws[k * NOUT + cg * 4];
#pragma unroll
        for (int n = 0; n < 8; n++) {
            float av = nb[n * NIN + k];
            acc[n].x += av * wv.x;
            acc[n].y += av * wv.y;
            acc[n].z += av * wv.z;
            acc[n].w += av * wv.w;
        }
    }

    float4 bv = *(const float4*)&b[cg * 4];
    __syncthreads();                         // done reading Ns; reuse as hvt
    float* hvt = Ns;
#pragma unroll
    for (int n = 0; n < 8; n++) {
        acc[n].x += bv.x; acc[n].y += bv.y; acc[n].z += bv.z; acc[n].w += bv.w;
        int node = base + ng * 8 + n;
        if (node < NN) {
            ((float4*)out)[(long)node * 32 + cg] = acc[n];   // out cols 0..63
            __half2 h01 = __floats2half2_rn(acc[n].x, acc[n].y);
            __half2 h23 = __floats2half2_rn(acc[n].z, acc[n].w);
            uint2 hv;
            hv.x = *reinterpret_cast<unsigned int*>(&h01);
            hv.y = *reinterpret_cast<unsigned int*>(&h23);
            ((uint2*)g_hvh)[(long)node * 16 + cg] = hv;      // halves 4cg..4cg+3
        }
        *(float4*)&hvt[(ng * 8 + n) * NOUT + cg * 4] = acc[n];
    }
    __syncthreads();

    // per-node scalars: 8 warps x 16 nodes each
    int wp = tid >> 5, l = tid & 31;
    float a1x = __ldg(&an[2*l]),      a1y = __ldg(&an[2*l+1]);
    float a2x = __ldg(&an[64 + 2*l]), a2y = __ldg(&an[64 + 2*l+1]);
#pragma unroll
    for (int i = 0; i < 16; i++) {
        int n = wp * 16 + i;
        int node = base + n;
        float2 h = ((const float2*)hvt)[n * 32 + l];
        float s1 = h.x * a1x + h.y * a1y;
        float s2 = h.x * a2x + h.y * a2y;
        float sq = h.x * h.x + h.y * h.y;
#pragma unroll
        for (int o = 16; o; o >>= 1) {
            s1 += __shfl_down_sync(FULLM, s1, o);
            s2 += __shfl_down_sync(FULLM, s2, o);
            sq += __shfl_down_sync(FULLM, sq, o);
        }
        if (l == 0 && node < NN) {
            g_s1[node] = s1; g_s2[node] = s2; g_hn[node] = sqrtf(sq);
        }
    }
}

// ---------------- kE: edge dot + attention (both dirs) + zero g_msg --------------
// Warp = 16 undirected edges (2KB coalesced ef read). All 32 lanes then own one
// (edge, direction) pair.
__global__ void kE_edge(const float* __restrict__ ef,
                        const float* __restrict__ an,
                        const int* __restrict__ p) {
    long gid = (long)blockIdx.x * blockDim.x + threadIdx.x;
    // zero msg: 800000 threads cover 800000 float4s exactly
    ((float4*)g_msg)[gid] = make_float4(0.f, 0.f, 0.f, 0.f);

    int w = (int)(gid >> 5);
    int l = threadIdx.x & 31;
    int row0 = w * 16;                       // NE % 16 == 0, grid exact
    const float4* ef4 = (const float4*)ef + (long)row0 * 8;
    float4 v0 = __ldg(&ef4[l]);
    float4 v1 = __ldg(&ef4[32 + l]);
    float4 v2 = __ldg(&ef4[64 + l]);
    float4 v3 = __ldg(&ef4[96 + l]);
    const float* a3 = an + 2 * NOUT;
    int q = l & 7;
    float ax = __ldg(&a3[4*q]),   ay = __ldg(&a3[4*q+1]);
    float az = __ldg(&a3[4*q+2]), aw = __ldg(&a3[4*q+3]);
    float s0 = v0.x*ax + v0.y*ay + v0.z*az + v0.w*aw;
    float s1 = v1.x*ax + v1.y*ay + v1.z*az + v1.w*aw;
    float s2 = v2.x*ax + v2.y*ay + v2.z*az + v2.w*aw;
    float s3 = v3.x*ax + v3.y*ay + v3.z*az + v3.w*aw;
#pragma unroll
    for (int o = 4; o; o >>= 1) {
        s0 += __shfl_xor_sync(FULLM, s0, o);
        s1 += __shfl_xor_sync(FULLM, s1, o);
        s2 += __shfl_xor_sync(FULLM, s2, o);
        s3 += __shfl_xor_sync(FULLM, s3, o);
    }
    int e = l & 15, dir = l >> 4;
    int srcl = (e & 3) << 3;
    float t0 = __shfl_sync(FULLM, s0, srcl);
    float t1 = __shfl_sync(FULLM, s1, srcl);
    float t2 = __shfl_sync(FULLM, s2, srcl);
    float t3 = __shfl_sync(FULLM, s3, srcl);
    int c = e >> 2;
    float tu = (c == 0) ? t0 : (c == 1) ? t1 : (c == 2) ? t2 : t3;

    int u = row0 + e;
    int2 xy = __ldg(&((const int2*)p)[u]);
    int src = dir ? xy.y : xy.x;
    int dst = dir ? xy.x : xy.y;
    float lg = __ldg(&g_s1[src]) + __ldg(&g_s2[dst]) + tu;
    float lr = (lg > 0.f) ? lg : ALPHA_L * lg;
    g_lr[u + dir * NE] = lr;
    atomicAdd(&g_attsum[src], __expf(lr));
}

// ---------------- k4: msg scatter (fp16 gather, vector RED) + var partials -------
#define ED 8   // undirected edges per warp
__global__ void k4_scatter(const int* __restrict__ p) {
    __shared__ float ssum[8], ssq[8];
    int warp = (blockIdx.x * blockDim.x + threadIdx.x) >> 5;
    int l = threadIdx.x & 31;
    int half = l >> 4, q = l & 15;
    long base = (long)warp * ED;           // NE % ED == 0, grid exact

    int2  xy[ED];
    float l1[ED], l2[ED];
#pragma unroll
    for (int e = 0; e < ED; e++) {
        long u = base + e;
        xy[e] = __ldg(&((const int2*)p)[u]);
        l1[e] = __ldg(&g_lr[u]);
        l2[e] = __ldg(&g_lr[u + NE]);
    }
    float a1[ED], a2[ED];
    uint2 h[ED];
#pragma unroll
    for (int e = 0; e < ED; e++) {
        a1[e] = __ldg(&g_attsum[xy[e].x]);
        a2[e] = __ldg(&g_attsum[xy[e].y]);
        int gdst = half ? xy[e].x : xy[e].y;
        h[e] = __ldg(&((const uint2*)g_hvh)[(long)gdst * 16 + q]);  // 4 halves
    }
    float vs = 0.f, vq = 0.f;
#pragma unroll
    for (int e = 0; e < ED; e++) {
        float an1 = l1[e] - __logf(a1[e]);
        float an2 = l2[e] - __logf(a2[e]);
        float an  = half ? an2 : an1;
        int gsrc  = half ? xy[e].y : xy[e].x;
        float2 f01 = __half22float2(u32_as_h2(h[e].x));
        float2 f23 = __half22float2(u32_as_h2(h[e].y));
        red_v4(&g_msg[(long)gsrc * NOUT + q * 4],
               make_float4(f01.x * an, f01.y * an, f23.x * an, f23.y * an));
        if (l == 0) { vs += an1 + an2; vq += an1 * an1 + an2 * an2; }
    }
    if (l == 0) { ssum[threadIdx.x >> 5] = vs; ssq[threadIdx.x >> 5] = vq; }
    __syncthreads();
    if (threadIdx.x == 0) {
        float bs = 0.f, bq = 0.f;
#pragma unroll
        for (int i = 0; i < 8; i++) { bs += ssum[i]; bq += ssq[i]; }
        atomicAdd(&g_psum[blockIdx.x & (NPART - 1)], (double)bs);
        atomicAdd(&g_psq [blockIdx.x & (NPART - 1)], (double)bq);
    }
}

// ---------------- k6: agg normalize + out[:,64:128]; block 0 also does variance --
__global__ void k6_final(float* __restrict__ out, const float* __restrict__ scale) {
    __shared__ double sd[NPART], qd[NPART];
    int lane = threadIdx.x & 31;
    int node = ((blockIdx.x * blockDim.x + threadIdx.x) >> 4);  // 16 lanes/node
    int q = lane & 15;
    float4 m = __ldg(&((const float4*)g_msg)[(long)node * 16 + q]);
    float sq = m.x*m.x + m.y*m.y + m.z*m.z + m.w*m.w;
#pragma unroll
    for (int o = 8; o; o >>= 1) sq += __shfl_xor_sync(FULLM, sq, o);
    float r = __ldg(&g_hn[node]) * __ldg(scale) / fmaxf(sqrtf(sq), EPSV);
    ((float4*)(out + (long)node * 128))[16 + q] =
        make_float4(m.x * r, m.y * r, m.z * r, m.w * r);

    if (blockIdx.x == 0) {
        int t = threadIdx.x;
        sd[t] = g_psum[t]; qd[t] = g_psq[t];
        __syncthreads();
        for (int o = NPART / 2; o; o >>= 1) {
            if (t < o) { sd[t] += sd[t + o]; qd[t] += qd[t + o]; }
            __syncthreads();
        }
        if (t == 0) {
            double E = (double)ND;
            double var = (qd[0] - sd[0] * sd[0] / E) / (E - 1.0);
            out[(long)NN * 128] = (float)var;
        }
    }
}

// ---------------- launch --------------------------------------------------------------
extern "C" void kernel_launch(void* const* d_in, const int* in_sizes, int n_in,
                              void* d_out, int out_size) {
    const float* nf    = (const float*)d_in[0];
    const float* ef    = (const float*)d_in[1];
    const int*   edges = (const int*)  d_in[2];
    const float* W     = (const float*)d_in[3];
    const float* b     = (const float*)d_in[4];
    const float* an    = (const float*)d_in[5];
    const float* scale = (const float*)d_in[6];
    float* out = (float*)d_out;

    const int k1_smem = (8192 + 16384) * 4;  // 96 KB
    cudaFuncSetAttribute(k1_gemm, cudaFuncAttributeMaxDynamicSharedMemorySize, k1_smem);

    k1_gemm   <<<(NN + 127)/128, 256, k1_smem>>>(nf, W, b, an, out);
    kE_edge   <<<NE/16/8, 256>>>(ef, an, edges);     // 3125 blocks, warp = 16 edges
    k4_scatter<<<NE/(8*ED), 256>>>(edges);           // 6250 blocks, warp = 8 edges
    k6_final  <<<NN/16, 256>>>(out, scale);          // 3125 blocks, 16 nodes/block
}